// round 2
// baseline (speedup 1.0000x reference)
#include <cuda_runtime.h>
#include <cuda_bf16.h>
#include <cstdint>

#define N_NODES_MAX 100000
#define DIM 64

// Scratch accumulators (alloc-free rule: __device__ globals).
__device__ float g_zr[N_NODES_MAX * DIM];
__device__ float g_zi[N_NODES_MAX * DIM];

// ---------------------------------------------------------------------------
// Zero the accumulators (float4 stores, both arrays in one grid-stride pass)
// ---------------------------------------------------------------------------
__global__ void zero_kernel(int n_elems) {
    int total4 = n_elems / 4;  // DIM=64 -> divisible by 4
    float4 z4 = make_float4(0.f, 0.f, 0.f, 0.f);
    float4* zr4 = reinterpret_cast<float4*>(g_zr);
    float4* zi4 = reinterpret_cast<float4*>(g_zi);
    for (int i = blockIdx.x * blockDim.x + threadIdx.x; i < total4;
         i += gridDim.x * blockDim.x) {
        zr4[i] = z4;
        zi4[i] = z4;
    }
}

// ---------------------------------------------------------------------------
// Edge phase: 16 threads per edge, float4 per thread (covers DIM=64).
//   e = d[dst]*d[src]*(wr + i*wi);  m = e * h[src];  z[dst] += m
// Scatter via red.global.add.v4.f32 (no-return vector reduction).
// ---------------------------------------------------------------------------
__global__ void edge_kernel(const float* __restrict__ hr,
                            const float* __restrict__ hi,
                            const float* __restrict__ d,
                            const float* __restrict__ wr,
                            const float* __restrict__ wi,
                            const int*   __restrict__ src,
                            const int*   __restrict__ dst,
                            int E) {
    int t = blockIdx.x * blockDim.x + threadIdx.x;
    int edge = t >> 4;
    int l16  = t & 15;
    if (edge >= E) return;

    int s  = src[edge];
    int dd = dst[edge];
    float coef = d[s] * d[dd];
    float er = coef * wr[edge];
    float ei = coef * wi[edge];

    const float4* hr4 = reinterpret_cast<const float4*>(hr + (size_t)s * DIM);
    const float4* hi4 = reinterpret_cast<const float4*>(hi + (size_t)s * DIM);
    float4 hrv = __ldg(&hr4[l16]);
    float4 hiv = __ldg(&hi4[l16]);

    float4 mr, mi;
    mr.x = er * hrv.x - ei * hiv.x;
    mr.y = er * hrv.y - ei * hiv.y;
    mr.z = er * hrv.z - ei * hiv.z;
    mr.w = er * hrv.w - ei * hiv.w;
    mi.x = ei * hrv.x + er * hiv.x;
    mi.y = ei * hrv.y + er * hiv.y;
    mi.z = ei * hrv.z + er * hiv.z;
    mi.w = ei * hrv.w + er * hiv.w;

    float* pr = g_zr + (size_t)dd * DIM + l16 * 4;
    float* pi = g_zi + (size_t)dd * DIM + l16 * 4;
    asm volatile("red.global.add.v4.f32 [%0], {%1,%2,%3,%4};"
                 :: "l"(pr), "f"(mr.x), "f"(mr.y), "f"(mr.z), "f"(mr.w)
                 : "memory");
    asm volatile("red.global.add.v4.f32 [%0], {%1,%2,%3,%4};"
                 :: "l"(pi), "f"(mi.x), "f"(mi.y), "f"(mi.z), "f"(mi.w)
                 : "memory");
}

// ---------------------------------------------------------------------------
// Node phase: per-row dense layer.
//   zr = (z_real @ W1^T + b1) - (z_imag @ W2^T + b2)
//   zi = (zr     @ W2^T + b2) + (z_imag @ W1^T + b1)
// One warp per row; lane j computes output columns j and j+32.
// W1/W2 in smem padded to 65 floats/row -> conflict-free lane-indexed reads.
// Grid-stride over rows so W is staged once per block.
// ---------------------------------------------------------------------------
#define NODE_WARPS 8

__global__ __launch_bounds__(NODE_WARPS * 32)
void node_kernel(const float* __restrict__ W1, const float* __restrict__ b1,
                 const float* __restrict__ W2, const float* __restrict__ b2,
                 float* __restrict__ out_zr, float* __restrict__ out_zi,
                 int n) {
    __shared__ float W1s[DIM][DIM + 1];
    __shared__ float W2s[DIM][DIM + 1];
    __shared__ float b1s[DIM], b2s[DIM];
    __shared__ float zbuf[NODE_WARPS][3][DIM];  // [warp][{real,imag,zr}][k]

    int tid = threadIdx.x;
    for (int idx = tid; idx < DIM * DIM; idx += blockDim.x) {
        W1s[idx >> 6][idx & 63] = W1[idx];
        W2s[idx >> 6][idx & 63] = W2[idx];
    }
    if (tid < DIM) { b1s[tid] = b1[tid]; b2s[tid] = b2[tid]; }
    __syncthreads();

    int lane = tid & 31;
    int w    = tid >> 5;
    int j  = lane;
    int j2 = lane + 32;

    for (int row = blockIdx.x * NODE_WARPS + w; row < n;
         row += gridDim.x * NODE_WARPS) {
        // stage z row (real+imag) into per-warp smem
        const float2* zr2 = reinterpret_cast<const float2*>(g_zr + (size_t)row * DIM);
        const float2* zi2 = reinterpret_cast<const float2*>(g_zi + (size_t)row * DIM);
        reinterpret_cast<float2*>(&zbuf[w][0][0])[lane] = zr2[lane];
        reinterpret_cast<float2*>(&zbuf[w][1][0])[lane] = zi2[lane];
        __syncwarp();

        // pass 1: zr
        float a0 = 0.f, a1 = 0.f, c0 = 0.f, c1 = 0.f;
        #pragma unroll
        for (int k = 0; k < DIM; k++) {
            float zrk = zbuf[w][0][k];
            float zik = zbuf[w][1][k];
            a0 += zrk * W1s[j][k];
            a1 += zrk * W1s[j2][k];
            c0 += zik * W2s[j][k];
            c1 += zik * W2s[j2][k];
        }
        float zr0 = (a0 + b1s[j])  - (c0 + b2s[j]);
        float zr1 = (a1 + b1s[j2]) - (c1 + b2s[j2]);
        zbuf[w][2][j]  = zr0;
        zbuf[w][2][j2] = zr1;
        __syncwarp();

        // pass 2: zi (uses NEW zr, matching the reference)
        float e0 = 0.f, e1 = 0.f, f0 = 0.f, f1 = 0.f;
        #pragma unroll
        for (int k = 0; k < DIM; k++) {
            float zrk = zbuf[w][2][k];
            float zik = zbuf[w][1][k];
            e0 += zrk * W2s[j][k];
            e1 += zrk * W2s[j2][k];
            f0 += zik * W1s[j][k];
            f1 += zik * W1s[j2][k];
        }
        float zi0 = (e0 + b2s[j])  + (f0 + b1s[j]);
        float zi1 = (e1 + b2s[j2]) + (f1 + b1s[j2]);

        float* orow = out_zr + (size_t)row * DIM;
        float* irow = out_zi + (size_t)row * DIM;
        orow[j]  = zr0;
        orow[j2] = zr1;
        irow[j]  = zi0;
        irow[j2] = zi1;
        __syncwarp();
    }
}

// ---------------------------------------------------------------------------
extern "C" void kernel_launch(void* const* d_in, const int* in_sizes, int n_in,
                              void* d_out, int out_size) {
    const float* h_real = (const float*)d_in[0];
    const float* h_imag = (const float*)d_in[1];
    const float* d      = (const float*)d_in[2];
    const float* w_real = (const float*)d_in[3];
    const float* w_imag = (const float*)d_in[4];
    const int*   src    = (const int*)  d_in[5];
    const int*   dst    = (const int*)  d_in[6];
    const float* W1     = (const float*)d_in[7];
    const float* b1     = (const float*)d_in[8];
    const float* W2     = (const float*)d_in[9];
    const float* b2     = (const float*)d_in[10];

    int n = in_sizes[2];          // N_NODES
    int E = in_sizes[3];          // N_EDGES

    float* out_zr = (float*)d_out;
    float* out_zi = (float*)d_out + (size_t)n * DIM;

    // 1) zero accumulators
    zero_kernel<<<1184, 256>>>(n * DIM);

    // 2) edge scatter
    {
        long long threads = (long long)E * 16;
        int blocks = (int)((threads + 255) / 256);
        edge_kernel<<<blocks, 256>>>(h_real, h_imag, d, w_real, w_imag,
                                     src, dst, E);
    }

    // 3) node dense layer
    node_kernel<<<592, NODE_WARPS * 32>>>(W1, b1, W2, b2, out_zr, out_zi, n);
}

// round 3
// speedup vs baseline: 1.0329x; 1.0329x over previous
#include <cuda_runtime.h>
#include <cuda_bf16.h>
#include <cstdint>

#define NMAX 100000
#define EMAX 1600000
#define DIM 64

// ---- scratch (__device__ globals; alloc-free rule) -------------------------
__device__ int    g_cnt[NMAX];      // per-node degree (histogram)
__device__ int    g_off[NMAX];      // exclusive offsets
__device__ int    g_cur[NMAX];      // write cursors for permute pass
__device__ int    g_part[128];      // chunk partial sums for scan
__device__ float4 g_pack[EMAX];     // sorted edge records: (src, er, ei, pad)

// ---------------------------------------------------------------------------
// K0: zero the histogram
// ---------------------------------------------------------------------------
__global__ void zero_cnt_kernel(int n) {
    int i = blockIdx.x * blockDim.x + threadIdx.x;
    if (i < n) g_cnt[i] = 0;
}

// ---------------------------------------------------------------------------
// K1: histogram of dst
// ---------------------------------------------------------------------------
__global__ void hist_kernel(const int* __restrict__ dst, int E) {
    int e = blockIdx.x * blockDim.x + threadIdx.x;
    if (e < E) atomicAdd(&g_cnt[dst[e]], 1);
}

// ---------------------------------------------------------------------------
// K2a: per-1024-chunk partial sums of g_cnt -> g_part
// ---------------------------------------------------------------------------
__global__ void scan_part_kernel(int n) {
    __shared__ int sdata[32];
    int i = blockIdx.x * 1024 + threadIdx.x;
    int lane = threadIdx.x & 31, w = threadIdx.x >> 5;
    int v = (i < n) ? g_cnt[i] : 0;
    #pragma unroll
    for (int o = 16; o > 0; o >>= 1) v += __shfl_down_sync(0xffffffffu, v, o);
    if (lane == 0) sdata[w] = v;
    __syncthreads();
    if (w == 0) {
        v = sdata[lane];
        #pragma unroll
        for (int o = 16; o > 0; o >>= 1) v += __shfl_down_sync(0xffffffffu, v, o);
        if (lane == 0) g_part[blockIdx.x] = v;
    }
}

// ---------------------------------------------------------------------------
// K2b: exclusive scan of g_part (nChunks <= 128), single block of 128
// ---------------------------------------------------------------------------
__global__ void scan_chunks_kernel(int nChunks) {
    int t = threadIdx.x;
    int lane = t & 31, w = t >> 5;
    int v = (t < nChunks) ? g_part[t] : 0;
    int x = v;
    #pragma unroll
    for (int o = 1; o < 32; o <<= 1) {
        int y = __shfl_up_sync(0xffffffffu, x, o);
        if (lane >= o) x += y;
    }
    __shared__ int ws[4];
    if (lane == 31) ws[w] = x;
    __syncthreads();
    int add = 0;
    for (int k = 0; k < w; k++) add += ws[k];
    if (t < nChunks) g_part[t] = (x + add) - v;  // exclusive
}

// ---------------------------------------------------------------------------
// K2c: per-chunk exclusive scan + chunk base -> g_off, g_cur
// ---------------------------------------------------------------------------
__global__ void scan_write_kernel(int n) {
    __shared__ int wsum[32];
    __shared__ int woff[32];
    int b = blockIdx.x;
    int i = b * 1024 + threadIdx.x;
    int lane = threadIdx.x & 31, w = threadIdx.x >> 5;
    int v = (i < n) ? g_cnt[i] : 0;
    int x = v;
    #pragma unroll
    for (int o = 1; o < 32; o <<= 1) {
        int y = __shfl_up_sync(0xffffffffu, x, o);
        if (lane >= o) x += y;
    }
    if (lane == 31) wsum[w] = x;
    __syncthreads();
    if (w == 0) {
        int y = wsum[lane];
        #pragma unroll
        for (int o = 1; o < 32; o <<= 1) {
            int z = __shfl_up_sync(0xffffffffu, y, o);
            if (lane >= o) y += z;
        }
        woff[lane] = y;  // inclusive warp-sum scan
    }
    __syncthreads();
    int base = ((w > 0) ? woff[w - 1] : 0) + g_part[b];
    int excl = base + x - v;
    if (i < n) { g_off[i] = excl; g_cur[i] = excl; }
}

// ---------------------------------------------------------------------------
// K3: compute per-edge coefficient and scatter packed record into dst-bin
// ---------------------------------------------------------------------------
__global__ void permute_kernel(const float* __restrict__ d,
                               const float* __restrict__ wr,
                               const float* __restrict__ wi,
                               const int*   __restrict__ src,
                               const int*   __restrict__ dst,
                               int E) {
    int e = blockIdx.x * blockDim.x + threadIdx.x;
    if (e >= E) return;
    int s  = src[e];
    int dd = dst[e];
    float coef = __ldg(&d[s]) * __ldg(&d[dd]);
    float er = coef * wr[e];
    float ei = coef * wi[e];
    int slot = atomicAdd(&g_cur[dd], 1);
    g_pack[slot] = make_float4(__int_as_float(s), er, ei, 0.f);
}

// ---------------------------------------------------------------------------
// K4: fused gather-reduce + dense layers.
//   Phase A: 16 threads/node accumulate z_real/z_imag in registers, spill to smem.
//   Phase B: 1 warp/node applies the two dependent 64x64 linears, writes out.
// ---------------------------------------------------------------------------
#define BLOCK 256
#define NODES_PER_BLOCK 16

__global__ __launch_bounds__(BLOCK)
void fused_kernel(const float* __restrict__ hr,
                  const float* __restrict__ hi,
                  const float* __restrict__ W1, const float* __restrict__ b1,
                  const float* __restrict__ W2, const float* __restrict__ b2,
                  float* __restrict__ out_zr, float* __restrict__ out_zi,
                  int n) {
    __shared__ float W1s[DIM][DIM + 1];
    __shared__ float W2s[DIM][DIM + 1];
    __shared__ float b1s[DIM], b2s[DIM];
    __shared__ float zs[NODES_PER_BLOCK][2][DIM];
    __shared__ float zrbuf[8][DIM];

    int tid = threadIdx.x;
    for (int idx = tid; idx < DIM * DIM; idx += BLOCK) {
        W1s[idx >> 6][idx & 63] = W1[idx];
        W2s[idx >> 6][idx & 63] = W2[idx];
    }
    if (tid < DIM) { b1s[tid] = b1[tid]; b2s[tid] = b2[tid]; }
    __syncthreads();

    int grp  = tid >> 4;   // 0..15 node group within block
    int l16  = tid & 15;
    int lane = tid & 31;
    int w    = tid >> 5;   // warp id 0..7

    const float4* hr4 = reinterpret_cast<const float4*>(hr);
    const float4* hi4 = reinterpret_cast<const float4*>(hi);

    int nTiles = (n + NODES_PER_BLOCK - 1) / NODES_PER_BLOCK;
    for (int tile = blockIdx.x; tile < nTiles; tile += gridDim.x) {
        // ---- Phase A: per-node edge reduction -----------------------------
        int node = tile * NODES_PER_BLOCK + grp;
        float4 azr = make_float4(0.f, 0.f, 0.f, 0.f);
        float4 azi = make_float4(0.f, 0.f, 0.f, 0.f);
        if (node < n) {
            int start = g_off[node];
            int deg   = g_cnt[node];
            const float4* packp = g_pack + start;
            #pragma unroll 4
            for (int t = 0; t < deg; t++) {
                float4 p = packp[t];
                int   s  = __float_as_int(p.x);
                float er = p.y, ei = p.z;
                float4 hrv = __ldg(hr4 + (size_t)s * 16 + l16);
                float4 hiv = __ldg(hi4 + (size_t)s * 16 + l16);
                azr.x += er * hrv.x - ei * hiv.x;
                azr.y += er * hrv.y - ei * hiv.y;
                azr.z += er * hrv.z - ei * hiv.z;
                azr.w += er * hrv.w - ei * hiv.w;
                azi.x += ei * hrv.x + er * hiv.x;
                azi.y += ei * hrv.y + er * hiv.y;
                azi.z += ei * hrv.z + er * hiv.z;
                azi.w += ei * hrv.w + er * hiv.w;
            }
        }
        reinterpret_cast<float4*>(&zs[grp][0][0])[l16] = azr;
        reinterpret_cast<float4*>(&zs[grp][1][0])[l16] = azi;
        __syncthreads();

        // ---- Phase B: dense layers (1 warp per node, 2 nodes per warp) ----
        for (int rr = w; rr < NODES_PER_BLOCK; rr += 8) {
            int node2 = tile * NODES_PER_BLOCK + rr;
            if (node2 < n) {
                int j = lane, j2 = lane + 32;
                // pass 1: zr = (z_r@W1^T+b1) - (z_i@W2^T+b2)
                float a0 = 0.f, a1 = 0.f, c0 = 0.f, c1 = 0.f;
                #pragma unroll
                for (int k = 0; k < DIM; k++) {
                    float zrk = zs[rr][0][k];
                    float zik = zs[rr][1][k];
                    a0 += zrk * W1s[j][k];
                    a1 += zrk * W1s[j2][k];
                    c0 += zik * W2s[j][k];
                    c1 += zik * W2s[j2][k];
                }
                float zr0 = (a0 + b1s[j])  - (c0 + b2s[j]);
                float zr1 = (a1 + b1s[j2]) - (c1 + b2s[j2]);
                zrbuf[w][j]  = zr0;
                zrbuf[w][j2] = zr1;
                __syncwarp();
                // pass 2: zi = (zr@W2^T+b2) + (z_i@W1^T+b1)  (uses NEW zr)
                float e0 = 0.f, e1 = 0.f, f0 = 0.f, f1 = 0.f;
                #pragma unroll
                for (int k = 0; k < DIM; k++) {
                    float zrk = zrbuf[w][k];
                    float zik = zs[rr][1][k];
                    e0 += zrk * W2s[j][k];
                    e1 += zrk * W2s[j2][k];
                    f0 += zik * W1s[j][k];
                    f1 += zik * W1s[j2][k];
                }
                float zi0 = (e0 + b2s[j])  + (f0 + b1s[j]);
                float zi1 = (e1 + b2s[j2]) + (f1 + b1s[j2]);

                float* orow = out_zr + (size_t)node2 * DIM;
                float* irow = out_zi + (size_t)node2 * DIM;
                orow[j]  = zr0;
                orow[j2] = zr1;
                irow[j]  = zi0;
                irow[j2] = zi1;
                __syncwarp();
            }
        }
        __syncthreads();  // protect zs before next tile
    }
}

// ---------------------------------------------------------------------------
extern "C" void kernel_launch(void* const* d_in, const int* in_sizes, int n_in,
                              void* d_out, int out_size) {
    const float* h_real = (const float*)d_in[0];
    const float* h_imag = (const float*)d_in[1];
    const float* d      = (const float*)d_in[2];
    const float* w_real = (const float*)d_in[3];
    const float* w_imag = (const float*)d_in[4];
    const int*   src    = (const int*)  d_in[5];
    const int*   dst    = (const int*)  d_in[6];
    const float* W1     = (const float*)d_in[7];
    const float* b1     = (const float*)d_in[8];
    const float* W2     = (const float*)d_in[9];
    const float* b2     = (const float*)d_in[10];

    int n = in_sizes[2];   // N_NODES
    int E = in_sizes[3];   // N_EDGES

    float* out_zr = (float*)d_out;
    float* out_zi = (float*)d_out + (size_t)n * DIM;

    int nChunks = (n + 1023) / 1024;

    zero_cnt_kernel<<<(n + 1023) / 1024, 1024>>>(n);
    hist_kernel<<<(E + 1023) / 1024, 1024>>>(dst, E);
    scan_part_kernel<<<nChunks, 1024>>>(n);
    scan_chunks_kernel<<<1, 128>>>(nChunks);
    scan_write_kernel<<<nChunks, 1024>>>(n);
    permute_kernel<<<(E + 255) / 256, 256>>>(d, w_real, w_imag, src, dst, E);
    fused_kernel<<<592, BLOCK>>>(h_real, h_imag, W1, b1, W2, b2,
                                 out_zr, out_zi, n);
}

// round 4
// speedup vs baseline: 1.5913x; 1.5407x over previous
#include <cuda_runtime.h>
#include <cuda_bf16.h>
#include <cstdint>

#define NMAX 100000
#define EMAX 1600000
#define DIM 64
#define PACKMAX (EMAX + 3 * NMAX + 64)

// ---- scratch (__device__ globals; alloc-free rule) -------------------------
__device__ int    g_cnt[NMAX];        // per-node real degree
__device__ int    g_off[NMAX];        // exclusive offsets (padded degrees)
__device__ int    g_cur[NMAX];        // write cursors
__device__ int    g_part[128];        // chunk partials for scan
__device__ float4 g_pack[PACKMAX];    // binned records: (src, er, ei, 0)
__device__ float  g_zr[NMAX * DIM];
__device__ float  g_zi[NMAX * DIM];

static __device__ __forceinline__ int round4(int x) { return (x + 3) & ~3; }

// ---------------------------------------------------------------------------
__global__ void zero_cnt_kernel(int n) {
    int i = blockIdx.x * blockDim.x + threadIdx.x;
    if (i < n) g_cnt[i] = 0;
}

__global__ void hist_kernel(const int* __restrict__ dst, int E) {
    int e = blockIdx.x * blockDim.x + threadIdx.x;
    if (e < E) atomicAdd(&g_cnt[dst[e]], 1);
}

// K2a: per-1024-chunk partial sums of padded counts
__global__ void scan_part_kernel(int n) {
    __shared__ int sdata[32];
    int i = blockIdx.x * 1024 + threadIdx.x;
    int lane = threadIdx.x & 31, w = threadIdx.x >> 5;
    int v = (i < n) ? round4(g_cnt[i]) : 0;
    #pragma unroll
    for (int o = 16; o > 0; o >>= 1) v += __shfl_down_sync(0xffffffffu, v, o);
    if (lane == 0) sdata[w] = v;
    __syncthreads();
    if (w == 0) {
        v = sdata[lane];
        #pragma unroll
        for (int o = 16; o > 0; o >>= 1) v += __shfl_down_sync(0xffffffffu, v, o);
        if (lane == 0) g_part[blockIdx.x] = v;
    }
}

// K2b: exclusive scan of chunk partials (<=128)
__global__ void scan_chunks_kernel(int nChunks) {
    int t = threadIdx.x;
    int lane = t & 31, w = t >> 5;
    int v = (t < nChunks) ? g_part[t] : 0;
    int x = v;
    #pragma unroll
    for (int o = 1; o < 32; o <<= 1) {
        int y = __shfl_up_sync(0xffffffffu, x, o);
        if (lane >= o) x += y;
    }
    __shared__ int ws[4];
    if (lane == 31) ws[w] = x;
    __syncthreads();
    int add = 0;
    for (int k = 0; k < w; k++) add += ws[k];
    if (t < nChunks) g_part[t] = (x + add) - v;
}

// K2c: per-chunk exclusive scan + base -> g_off, g_cur
__global__ void scan_write_kernel(int n) {
    __shared__ int wsum[32];
    __shared__ int woff[32];
    int b = blockIdx.x;
    int i = b * 1024 + threadIdx.x;
    int lane = threadIdx.x & 31, w = threadIdx.x >> 5;
    int v = (i < n) ? round4(g_cnt[i]) : 0;
    int x = v;
    #pragma unroll
    for (int o = 1; o < 32; o <<= 1) {
        int y = __shfl_up_sync(0xffffffffu, x, o);
        if (lane >= o) x += y;
    }
    if (lane == 31) wsum[w] = x;
    __syncthreads();
    if (w == 0) {
        int y = wsum[lane];
        #pragma unroll
        for (int o = 1; o < 32; o <<= 1) {
            int z = __shfl_up_sync(0xffffffffu, y, o);
            if (lane >= o) y += z;
        }
        woff[lane] = y;
    }
    __syncthreads();
    int base = ((w > 0) ? woff[w - 1] : 0) + g_part[b];
    int excl = base + x - v;
    if (i < n) { g_off[i] = excl; g_cur[i] = excl; }
}

// K2d: zero-fill padding slots (coef 0, src 0 -> harmless)
__global__ void pad_kernel(int n) {
    int i = blockIdx.x * blockDim.x + threadIdx.x;
    if (i >= n) return;
    int deg = g_cnt[i], off = g_off[i];
    int d4 = round4(deg);
    for (int t = deg; t < d4; t++)
        g_pack[off + t] = make_float4(0.f, 0.f, 0.f, 0.f);
}

// K3: scatter packed records into dst bins.  Coefficient excludes d[dst]
// (applied once per node in the edge kernel).
__global__ void permute_kernel(const float* __restrict__ d,
                               const float* __restrict__ wr,
                               const float* __restrict__ wi,
                               const int*   __restrict__ src,
                               const int*   __restrict__ dst,
                               int E) {
    int e = blockIdx.x * blockDim.x + threadIdx.x;
    if (e >= E) return;
    int s  = src[e];
    int dd = dst[e];
    float ds = __ldg(&d[s]);
    int slot = atomicAdd(&g_cur[dd], 1);
    g_pack[slot] = make_float4(__int_as_float(s), ds * wr[e], ds * wi[e], 0.f);
}

// ---------------------------------------------------------------------------
// K4: edge gather-reduce.  16 threads per node, batch-prefetch 16 records
// coalesced, broadcast via width-16 shuffles -> all gathers independent.
// ---------------------------------------------------------------------------
__global__ __launch_bounds__(256)
void edge_kernel(const float* __restrict__ hr,
                 const float* __restrict__ hi,
                 const float* __restrict__ d,
                 int n) {
    int node = blockIdx.x * 16 + (threadIdx.x >> 4);
    int l16  = threadIdx.x & 15;
    unsigned hmask = (threadIdx.x & 16) ? 0xFFFF0000u : 0x0000FFFFu;

    const float4* hr4 = reinterpret_cast<const float4*>(hr);
    const float4* hi4 = reinterpret_cast<const float4*>(hi);

    int deg4 = 0, start = 0;
    if (node < n) {
        start = g_off[node];
        deg4  = round4(g_cnt[node]);
    }
    const float4* packp = g_pack + start;

    float4 ar = make_float4(0.f, 0.f, 0.f, 0.f);
    float4 ai = make_float4(0.f, 0.f, 0.f, 0.f);

    for (int base = 0; base < deg4; base += 16) {
        int m = min(16, deg4 - base);   // multiple of 4
        float4 p = make_float4(0.f, 0.f, 0.f, 0.f);
        if (l16 < m) p = __ldg(&packp[base + l16]);
        int ps = __float_as_int(p.x);

        #pragma unroll
        for (int c = 0; c < 4; c++) {
            if (c * 4 < m) {
                #pragma unroll
                for (int qq = 0; qq < 4; qq++) {
                    int q = c * 4 + qq;
                    int   s  = __shfl_sync(hmask, ps,  q, 16);
                    float er = __shfl_sync(hmask, p.y, q, 16);
                    float ei = __shfl_sync(hmask, p.z, q, 16);
                    float4 hrv = __ldg(hr4 + ((size_t)s << 4) + l16);
                    float4 hiv = __ldg(hi4 + ((size_t)s << 4) + l16);
                    ar.x += er * hrv.x - ei * hiv.x;
                    ar.y += er * hrv.y - ei * hiv.y;
                    ar.z += er * hrv.z - ei * hiv.z;
                    ar.w += er * hrv.w - ei * hiv.w;
                    ai.x += ei * hrv.x + er * hiv.x;
                    ai.y += ei * hrv.y + er * hiv.y;
                    ai.z += ei * hrv.z + er * hiv.z;
                    ai.w += ei * hrv.w + er * hiv.w;
                }
            }
        }
    }

    if (node < n) {
        float dn = __ldg(&d[node]);
        ar.x *= dn; ar.y *= dn; ar.z *= dn; ar.w *= dn;
        ai.x *= dn; ai.y *= dn; ai.z *= dn; ai.w *= dn;
        reinterpret_cast<float4*>(g_zr + (size_t)node * DIM)[l16] = ar;
        reinterpret_cast<float4*>(g_zi + (size_t)node * DIM)[l16] = ai;
    }
}

// ---------------------------------------------------------------------------
// K5: node dense layers, register-blocked 8 rows per warp (FMA-bound).
//   zr = (z_r@W1^T+b1) - (z_i@W2^T+b2)
//   zi = (zr @W2^T+b2) + (z_i@W1^T+b1)   (uses NEW zr)
// W padded to 68 floats/row -> conflict-free lane-indexed LDS.128.
// ---------------------------------------------------------------------------
#define NW  8
#define RPW 8
#define WPAD 68

__global__ __launch_bounds__(NW * 32)
void node_kernel(const float* __restrict__ W1, const float* __restrict__ b1,
                 const float* __restrict__ W2, const float* __restrict__ b2,
                 float* __restrict__ out_zr, float* __restrict__ out_zi,
                 int n) {
    extern __shared__ float smf[];
    float* W1s = smf;                       // [64][68]
    float* W2s = W1s + DIM * WPAD;          // [64][68]
    float* b1s = W2s + DIM * WPAD;          // [64]
    float* b2s = b1s + DIM;                 // [64]
    float* zsr = b2s + DIM;                 // [NW][RPW][64]
    float* zsi = zsr + NW * RPW * DIM;      // [NW][RPW][64]
    float* zrb = zsi + NW * RPW * DIM;      // [NW][RPW][64]

    int tid = threadIdx.x;
    for (int idx = tid; idx < DIM * DIM; idx += NW * 32) {
        W1s[(idx >> 6) * WPAD + (idx & 63)] = W1[idx];
        W2s[(idx >> 6) * WPAD + (idx & 63)] = W2[idx];
    }
    if (tid < DIM) { b1s[tid] = b1[tid]; b2s[tid] = b2[tid]; }
    __syncthreads();

    int lane = tid & 31;
    int w    = tid >> 5;
    int j  = lane, j2 = lane + 32;
    float* my_zsr = zsr + w * RPW * DIM;
    float* my_zsi = zsi + w * RPW * DIM;
    float* my_zrb = zrb + w * RPW * DIM;

    int nChunk = (n + RPW - 1) / RPW;
    for (int ch = blockIdx.x * NW + w; ch < nChunk; ch += gridDim.x * NW) {
        int rbase = ch * RPW;
        // stage z rows (coalesced float2 per lane per row)
        #pragma unroll
        for (int r = 0; r < RPW; r++) {
            int row = rbase + r;
            if (row < n) {
                reinterpret_cast<float2*>(my_zsr + r * DIM)[lane] =
                    reinterpret_cast<const float2*>(g_zr + (size_t)row * DIM)[lane];
                reinterpret_cast<float2*>(my_zsi + r * DIM)[lane] =
                    reinterpret_cast<const float2*>(g_zi + (size_t)row * DIM)[lane];
            }
        }
        __syncwarp();

        // ---- pass 1: zr ----
        float a0[RPW], a1[RPW];
        #pragma unroll
        for (int r = 0; r < RPW; r++) { a0[r] = 0.f; a1[r] = 0.f; }
        #pragma unroll 4
        for (int k4 = 0; k4 < 16; k4++) {
            float4 w1a = *reinterpret_cast<const float4*>(W1s + j  * WPAD + k4 * 4);
            float4 w1b = *reinterpret_cast<const float4*>(W1s + j2 * WPAD + k4 * 4);
            float4 w2a = *reinterpret_cast<const float4*>(W2s + j  * WPAD + k4 * 4);
            float4 w2b = *reinterpret_cast<const float4*>(W2s + j2 * WPAD + k4 * 4);
            #pragma unroll
            for (int r = 0; r < RPW; r++) {
                float4 zr4 = reinterpret_cast<const float4*>(my_zsr + r * DIM)[k4];
                float4 zi4 = reinterpret_cast<const float4*>(my_zsi + r * DIM)[k4];
                a0[r] += zr4.x * w1a.x - zi4.x * w2a.x;
                a0[r] += zr4.y * w1a.y - zi4.y * w2a.y;
                a0[r] += zr4.z * w1a.z - zi4.z * w2a.z;
                a0[r] += zr4.w * w1a.w - zi4.w * w2a.w;
                a1[r] += zr4.x * w1b.x - zi4.x * w2b.x;
                a1[r] += zr4.y * w1b.y - zi4.y * w2b.y;
                a1[r] += zr4.z * w1b.z - zi4.z * w2b.z;
                a1[r] += zr4.w * w1b.w - zi4.w * w2b.w;
            }
        }
        #pragma unroll
        for (int r = 0; r < RPW; r++) {
            int row = rbase + r;
            float zr0 = (a0[r] + b1s[j])  - b2s[j];
            float zr1 = (a1[r] + b1s[j2]) - b2s[j2];
            my_zrb[r * DIM + j]  = zr0;
            my_zrb[r * DIM + j2] = zr1;
            if (row < n) {
                out_zr[(size_t)row * DIM + j]  = zr0;
                out_zr[(size_t)row * DIM + j2] = zr1;
            }
        }
        __syncwarp();

        // ---- pass 2: zi (uses NEW zr) ----
        #pragma unroll
        for (int r = 0; r < RPW; r++) { a0[r] = 0.f; a1[r] = 0.f; }
        #pragma unroll 4
        for (int k4 = 0; k4 < 16; k4++) {
            float4 w1a = *reinterpret_cast<const float4*>(W1s + j  * WPAD + k4 * 4);
            float4 w1b = *reinterpret_cast<const float4*>(W1s + j2 * WPAD + k4 * 4);
            float4 w2a = *reinterpret_cast<const float4*>(W2s + j  * WPAD + k4 * 4);
            float4 w2b = *reinterpret_cast<const float4*>(W2s + j2 * WPAD + k4 * 4);
            #pragma unroll
            for (int r = 0; r < RPW; r++) {
                float4 zr4 = reinterpret_cast<const float4*>(my_zrb + r * DIM)[k4];
                float4 zi4 = reinterpret_cast<const float4*>(my_zsi + r * DIM)[k4];
                a0[r] += zr4.x * w2a.x + zi4.x * w1a.x;
                a0[r] += zr4.y * w2a.y + zi4.y * w1a.y;
                a0[r] += zr4.z * w2a.z + zi4.z * w1a.z;
                a0[r] += zr4.w * w2a.w + zi4.w * w1a.w;
                a1[r] += zr4.x * w2b.x + zi4.x * w1b.x;
                a1[r] += zr4.y * w2b.y + zi4.y * w1b.y;
                a1[r] += zr4.z * w2b.z + zi4.z * w1b.z;
                a1[r] += zr4.w * w2b.w + zi4.w * w1b.w;
            }
        }
        #pragma unroll
        for (int r = 0; r < RPW; r++) {
            int row = rbase + r;
            if (row < n) {
                out_zi[(size_t)row * DIM + j]  = (a0[r] + b2s[j])  + b1s[j];
                out_zi[(size_t)row * DIM + j2] = (a1[r] + b2s[j2]) + b1s[j2];
            }
        }
        __syncwarp();
    }
}

// ---------------------------------------------------------------------------
extern "C" void kernel_launch(void* const* d_in, const int* in_sizes, int n_in,
                              void* d_out, int out_size) {
    const float* h_real = (const float*)d_in[0];
    const float* h_imag = (const float*)d_in[1];
    const float* d      = (const float*)d_in[2];
    const float* w_real = (const float*)d_in[3];
    const float* w_imag = (const float*)d_in[4];
    const int*   src    = (const int*)  d_in[5];
    const int*   dst    = (const int*)  d_in[6];
    const float* W1     = (const float*)d_in[7];
    const float* b1     = (const float*)d_in[8];
    const float* W2     = (const float*)d_in[9];
    const float* b2     = (const float*)d_in[10];

    int n = in_sizes[2];   // N_NODES
    int E = in_sizes[3];   // N_EDGES

    float* out_zr = (float*)d_out;
    float* out_zi = (float*)d_out + (size_t)n * DIM;

    int nChunks = (n + 1023) / 1024;

    zero_cnt_kernel<<<(n + 1023) / 1024, 1024>>>(n);
    hist_kernel<<<(E + 1023) / 1024, 1024>>>(dst, E);
    scan_part_kernel<<<nChunks, 1024>>>(n);
    scan_chunks_kernel<<<1, 128>>>(nChunks);
    scan_write_kernel<<<nChunks, 1024>>>(n);
    pad_kernel<<<(n + 255) / 256, 256>>>(n);
    permute_kernel<<<(E + 255) / 256, 256>>>(d, w_real, w_imag, src, dst, E);
    edge_kernel<<<(n + 15) / 16, 256>>>(h_real, h_imag, d, n);

    size_t node_smem = (size_t)(2 * DIM * WPAD + 2 * DIM + 3 * NW * RPW * DIM)
                       * sizeof(float);
    cudaFuncSetAttribute(node_kernel,
                         cudaFuncAttributeMaxDynamicSharedMemorySize,
                         (int)node_smem);
    node_kernel<<<296, NW * 32, node_smem>>>(W1, b1, W2, b2,
                                             out_zr, out_zi, n);
}